// round 1
// baseline (speedup 1.0000x reference)
#include <cuda_runtime.h>
#include <cuda_bf16.h>
#include <cstddef>

// Problem dims (fixed for this problem instance)
#define B_DIM  4096
#define H_DIM  1024
#define FOURH  4096
#define K_DIM  2048   // I + H

// Scratch for ifgo pre-activations: 4096 x 4096 fp32 = 64 MB.
// __device__ global (no dynamic allocation — allowed by harness rules).
__device__ float g_ifgo[(size_t)B_DIM * FOURH];

// ---------------------------------------------------------------------------
// Kernel 1: fused dual-GEMM  ifgo = [x | h] @ [w_i ; w_h] + (b_i + b_h)
// Classic 128x128x16 SGEMM, 256 threads, 8x8 register tile per thread.
// ---------------------------------------------------------------------------
constexpr int BM = 128, BN = 128, BK = 16, TM = 8, TN = 8;

__global__ __launch_bounds__(256, 2)
void lstm_gemm_kernel(const float* __restrict__ x,
                      const float* __restrict__ h,
                      const float* __restrict__ wi,
                      const float* __restrict__ wh,
                      const float* __restrict__ bi,
                      const float* __restrict__ bh)
{
    __shared__ float As[BK][BM];   // A tile stored transposed (k-major)
    __shared__ float Bs[BK][BN];

    const int tid = threadIdx.x;
    const int bm  = blockIdx.y * BM;
    const int bn  = blockIdx.x * BN;
    const int tx  = tid & 15;      // 0..15 -> N direction
    const int ty  = tid >> 4;      // 0..15 -> M direction

    float acc[TM][TN];
    #pragma unroll
    for (int i = 0; i < TM; i++)
        #pragma unroll
        for (int j = 0; j < TN; j++)
            acc[i][j] = 0.0f;

    for (int k0 = 0; k0 < K_DIM; k0 += BK) {
        // ---- Load A tile: rows [bm, bm+128), cols [k0, k0+16) ----
        // 128*16 = 2048 floats = 512 float4; 256 threads x 2.
        #pragma unroll
        for (int i = 0; i < 2; i++) {
            int idx = tid + i * 256;
            int row = idx >> 2;            // 0..127
            int kc  = (idx & 3) * 4;       // 0,4,8,12
            int gk  = k0 + kc;
            const float* src = (gk < H_DIM)
                ? &x[(size_t)(bm + row) * H_DIM + gk]
                : &h[(size_t)(bm + row) * H_DIM + (gk - H_DIM)];
            float4 v = *(const float4*)src;
            As[kc + 0][row] = v.x;
            As[kc + 1][row] = v.y;
            As[kc + 2][row] = v.z;
            As[kc + 3][row] = v.w;
        }
        // ---- Load B tile: rows [k0, k0+16), cols [bn, bn+128) ----
        #pragma unroll
        for (int i = 0; i < 2; i++) {
            int idx = tid + i * 256;
            int kr  = idx >> 5;            // 0..15
            int col = (idx & 31) * 4;      // 0..124
            int gk  = k0 + kr;
            const float* src = (gk < H_DIM)
                ? &wi[(size_t)gk * FOURH + bn + col]
                : &wh[(size_t)(gk - H_DIM) * FOURH + bn + col];
            *(float4*)&Bs[kr][col] = *(const float4*)src;
        }
        __syncthreads();

        // ---- Compute ----
        #pragma unroll
        for (int k = 0; k < BK; k++) {
            float a[TM], b[TN];
            float4 a0 = *(const float4*)&As[k][ty * TM];
            float4 a1 = *(const float4*)&As[k][ty * TM + 4];
            a[0]=a0.x; a[1]=a0.y; a[2]=a0.z; a[3]=a0.w;
            a[4]=a1.x; a[5]=a1.y; a[6]=a1.z; a[7]=a1.w;
            float4 b0 = *(const float4*)&Bs[k][tx * TN];
            float4 b1 = *(const float4*)&Bs[k][tx * TN + 4];
            b[0]=b0.x; b[1]=b0.y; b[2]=b0.z; b[3]=b0.w;
            b[4]=b1.x; b[5]=b1.y; b[6]=b1.z; b[7]=b1.w;
            #pragma unroll
            for (int i = 0; i < TM; i++)
                #pragma unroll
                for (int j = 0; j < TN; j++)
                    acc[i][j] = fmaf(a[i], b[j], acc[i][j]);
        }
        __syncthreads();
    }

    // ---- Epilogue: + (b_i + b_h), write to scratch ----
    #pragma unroll
    for (int i = 0; i < TM; i++) {
        int row = bm + ty * TM + i;
        #pragma unroll
        for (int j = 0; j < TN; j += 4) {
            int col = bn + tx * TN + j;
            float4 bias;
            bias.x = bi[col + 0] + bh[col + 0];
            bias.y = bi[col + 1] + bh[col + 1];
            bias.z = bi[col + 2] + bh[col + 2];
            bias.w = bi[col + 3] + bh[col + 3];
            float4 v;
            v.x = acc[i][j + 0] + bias.x;
            v.y = acc[i][j + 1] + bias.y;
            v.z = acc[i][j + 2] + bias.z;
            v.w = acc[i][j + 3] + bias.w;
            *(float4*)&g_ifgo[(size_t)row * FOURH + col] = v;
        }
    }
}

// ---------------------------------------------------------------------------
// Kernel 2: pointwise LSTM gates.
//   i = sigmoid(ifgo[:, 0:H]);  f = sigmoid(ifgo[:, H:2H])
//   g = tanh  (ifgo[:, 2H:3H]); o = sigmoid(ifgo[:, 3H:4H])
//   c_new = f*c + i*g;  h_new = o*tanh(c_new)
// Output layout: [h_new (B*H) | c_new (B*H)]
// ---------------------------------------------------------------------------
__device__ __forceinline__ float sigmoidf_fast(float v) {
    return 1.0f / (1.0f + __expf(-v));
}

__global__ __launch_bounds__(256)
void lstm_gates_kernel(const float* __restrict__ c_t, float* __restrict__ out)
{
    int idx = blockIdx.x * blockDim.x + threadIdx.x;   // over B*H/4
    const int per_row = H_DIM / 4;
    if (idx >= B_DIM * per_row) return;
    int b  = idx / per_row;
    int hc = (idx - b * per_row) * 4;

    size_t base = (size_t)b * FOURH;
    float4 iv = *(const float4*)&g_ifgo[base + 0 * H_DIM + hc];
    float4 fv = *(const float4*)&g_ifgo[base + 1 * H_DIM + hc];
    float4 gv = *(const float4*)&g_ifgo[base + 2 * H_DIM + hc];
    float4 ov = *(const float4*)&g_ifgo[base + 3 * H_DIM + hc];
    float4 cv = *(const float4*)&c_t[(size_t)b * H_DIM + hc];

    float iarr[4] = {iv.x, iv.y, iv.z, iv.w};
    float farr[4] = {fv.x, fv.y, fv.z, fv.w};
    float garr[4] = {gv.x, gv.y, gv.z, gv.w};
    float oarr[4] = {ov.x, ov.y, ov.z, ov.w};
    float carr[4] = {cv.x, cv.y, cv.z, cv.w};
    float hn[4], cn[4];
    #pragma unroll
    for (int l = 0; l < 4; l++) {
        float ig = sigmoidf_fast(iarr[l]);
        float fg = sigmoidf_fast(farr[l]);
        float gg = tanhf(garr[l]);
        float og = sigmoidf_fast(oarr[l]);
        float c_new = fg * carr[l] + ig * gg;
        cn[l] = c_new;
        hn[l] = og * tanhf(c_new);
    }

    float4 hv = {hn[0], hn[1], hn[2], hn[3]};
    float4 cvo = {cn[0], cn[1], cn[2], cn[3]};
    *(float4*)&out[(size_t)b * H_DIM + hc] = hv;
    *(float4*)&out[(size_t)B_DIM * H_DIM + (size_t)b * H_DIM + hc] = cvo;
}

// ---------------------------------------------------------------------------
// Launch
// Inputs (metadata order): input, h_t, c_t, w_i, w_h, b_i, b_h
// ---------------------------------------------------------------------------
extern "C" void kernel_launch(void* const* d_in, const int* in_sizes, int n_in,
                              void* d_out, int out_size)
{
    const float* x   = (const float*)d_in[0];
    const float* h_t = (const float*)d_in[1];
    const float* c_t = (const float*)d_in[2];
    const float* w_i = (const float*)d_in[3];
    const float* w_h = (const float*)d_in[4];
    const float* b_i = (const float*)d_in[5];
    const float* b_h = (const float*)d_in[6];
    float* out = (float*)d_out;

    dim3 grid(FOURH / BN, B_DIM / BM);   // 32 x 32
    lstm_gemm_kernel<<<grid, 256>>>(x, h_t, w_i, w_h, b_i, b_h);

    int n4 = B_DIM * (H_DIM / 4);
    lstm_gates_kernel<<<(n4 + 255) / 256, 256>>>(c_t, out);
}

// round 2
// speedup vs baseline: 3.4882x; 3.4882x over previous
#include <cuda_runtime.h>
#include <cuda_bf16.h>
#include <cstddef>
#include <cstdint>

// Problem dims (fixed)
#define B_DIM  4096
#define H_DIM  1024
#define FOURH  4096
#define K_DIM  2048

// Scratch for ifgo pre-activations (64 MB) — __device__ global, allowed.
__device__ float g_ifgo[(size_t)B_DIM * FOURH];

// Tile config
#define BM  128
#define BN  128
#define BK  16
#define LDA 20     // BK + 4  -> A-fragment LDS conflict-free (20g+tig distinct mod 32)
#define LDB 136    // BN + 8  -> B-fragment LDS conflict-free (8*tig+g distinct mod 32)

__device__ __forceinline__ uint32_t cvt_tf32(float x) {
    uint32_t r;
    asm("cvt.rna.tf32.f32 %0, %1;" : "=r"(r) : "f"(x));
    return r;
}

__device__ __forceinline__ void cp_async16(void* smem_dst, const void* gsrc) {
    uint32_t s = (uint32_t)__cvta_generic_to_shared(smem_dst);
    asm volatile("cp.async.cg.shared.global [%0], [%1], 16;\n" :: "r"(s), "l"(gsrc));
}

// ---------------------------------------------------------------------------
// TF32 tensor-core dual-GEMM: ifgo = [x | h] @ [w_i ; w_h]   (bias added later)
// CTA 128x128, BK=16, 4 warps (each 64x64), double-buffered cp.async.
// ---------------------------------------------------------------------------
__global__ __launch_bounds__(128, 2)
void lstm_gemm_tf32(const float* __restrict__ x, const float* __restrict__ h,
                    const float* __restrict__ wi, const float* __restrict__ wh)
{
    __shared__ float As[2][BM][LDA];   // row-major A tile (m, k)
    __shared__ float Bs[2][BK][LDB];   // row-major B tile (k, n)

    const int tid  = threadIdx.x;
    const int lane = tid & 31;
    const int wid  = tid >> 5;
    const int g    = lane >> 2;   // 0..7
    const int tig  = lane & 3;    // 0..3
    const int wm   = (wid >> 1) * 64;   // warp M offset within CTA tile
    const int wn   = (wid & 1) * 64;    // warp N offset
    const int bm   = blockIdx.y * BM;
    const int bn   = blockIdx.x * BN;

    float acc[4][8][4];
    #pragma unroll
    for (int mt = 0; mt < 4; mt++)
        #pragma unroll
        for (int nt = 0; nt < 8; nt++)
            #pragma unroll
            for (int e = 0; e < 4; e++)
                acc[mt][nt][e] = 0.0f;

    const int NIT = K_DIM / BK;   // 128

    // ---- stage loader (k0 = global k offset) ----
    // A: 128 rows x 16 cols = 512 float4 chunks; B: 16 rows x 128 cols = 512 chunks
    #define LOAD_STAGE(s, k0)                                                    \
    do {                                                                         \
        const float* abase; int acol;                                            \
        if ((k0) < H_DIM) { abase = x;  acol = (k0); }                           \
        else              { abase = h;  acol = (k0) - H_DIM; }                   \
        _Pragma("unroll")                                                        \
        for (int i = 0; i < 4; i++) {                                            \
            int c  = tid + i * 128;                                              \
            int r  = c >> 2;                                                     \
            int c4 = (c & 3) * 4;                                                \
            cp_async16(&As[s][r][c4],                                            \
                       &abase[(size_t)(bm + r) * H_DIM + acol + c4]);            \
        }                                                                        \
        const float* bbase; int brow;                                            \
        if ((k0) < H_DIM) { bbase = wi; brow = (k0); }                           \
        else              { bbase = wh; brow = (k0) - H_DIM; }                   \
        _Pragma("unroll")                                                        \
        for (int i = 0; i < 4; i++) {                                            \
            int c  = tid + i * 128;                                              \
            int kr = c >> 5;                                                     \
            int cc = (c & 31) * 4;                                               \
            cp_async16(&Bs[s][kr][cc],                                           \
                       &bbase[(size_t)(brow + kr) * FOURH + bn + cc]);           \
        }                                                                        \
        asm volatile("cp.async.commit_group;\n" ::: "memory");                   \
    } while (0)

    LOAD_STAGE(0, 0);

    for (int it = 0; it < NIT; it++) {
        const int cur = it & 1;
        if (it + 1 < NIT) {
            LOAD_STAGE((it + 1) & 1, (it + 1) * BK);
            asm volatile("cp.async.wait_group 1;\n" ::: "memory");
        } else {
            asm volatile("cp.async.wait_group 0;\n" ::: "memory");
        }
        __syncthreads();

        #pragma unroll
        for (int kk = 0; kk < BK; kk += 8) {
            uint32_t afrag[4][4];
            #pragma unroll
            for (int mt = 0; mt < 4; mt++) {
                int am = wm + mt * 16;
                afrag[mt][0] = cvt_tf32(As[cur][am + g    ][kk + tig    ]);
                afrag[mt][1] = cvt_tf32(As[cur][am + g + 8][kk + tig    ]);
                afrag[mt][2] = cvt_tf32(As[cur][am + g    ][kk + tig + 4]);
                afrag[mt][3] = cvt_tf32(As[cur][am + g + 8][kk + tig + 4]);
            }
            uint32_t bfrag[8][2];
            #pragma unroll
            for (int nt = 0; nt < 8; nt++) {
                int bc = wn + nt * 8 + g;
                bfrag[nt][0] = cvt_tf32(Bs[cur][kk + tig    ][bc]);
                bfrag[nt][1] = cvt_tf32(Bs[cur][kk + tig + 4][bc]);
            }
            #pragma unroll
            for (int mt = 0; mt < 4; mt++)
                #pragma unroll
                for (int nt = 0; nt < 8; nt++) {
                    asm volatile(
                        "mma.sync.aligned.m16n8k8.row.col.f32.tf32.tf32.f32 "
                        "{%0,%1,%2,%3}, {%4,%5,%6,%7}, {%8,%9}, {%0,%1,%2,%3};\n"
                        : "+f"(acc[mt][nt][0]), "+f"(acc[mt][nt][1]),
                          "+f"(acc[mt][nt][2]), "+f"(acc[mt][nt][3])
                        : "r"(afrag[mt][0]), "r"(afrag[mt][1]),
                          "r"(afrag[mt][2]), "r"(afrag[mt][3]),
                          "r"(bfrag[nt][0]), "r"(bfrag[nt][1]));
                }
        }
        __syncthreads();
    }
    #undef LOAD_STAGE

    // ---- epilogue: write raw ifgo (bias folded into gates kernel) ----
    #pragma unroll
    for (int mt = 0; mt < 4; mt++) {
        int r0 = bm + wm + mt * 16 + g;
        #pragma unroll
        for (int nt = 0; nt < 8; nt++) {
            int c0 = bn + wn + nt * 8 + tig * 2;
            float2 v0 = make_float2(acc[mt][nt][0], acc[mt][nt][1]);
            float2 v1 = make_float2(acc[mt][nt][2], acc[mt][nt][3]);
            *(float2*)&g_ifgo[(size_t)r0       * FOURH + c0] = v0;
            *(float2*)&g_ifgo[(size_t)(r0 + 8) * FOURH + c0] = v1;
        }
    }
}

// ---------------------------------------------------------------------------
// Pointwise LSTM gates (adds bias here).
// Output layout: [h_new (B*H) | c_new (B*H)]
// ---------------------------------------------------------------------------
__device__ __forceinline__ float sigmoidf_fast(float v) {
    return 1.0f / (1.0f + __expf(-v));
}

__global__ __launch_bounds__(256)
void lstm_gates_kernel(const float* __restrict__ c_t,
                       const float* __restrict__ bi,
                       const float* __restrict__ bh,
                       float* __restrict__ out)
{
    int idx = blockIdx.x * blockDim.x + threadIdx.x;   // over B*H/4
    const int per_row = H_DIM / 4;
    if (idx >= B_DIM * per_row) return;
    int b  = idx / per_row;
    int hc = (idx - b * per_row) * 4;

    size_t base = (size_t)b * FOURH;
    float4 iv = *(const float4*)&g_ifgo[base + 0 * H_DIM + hc];
    float4 fv = *(const float4*)&g_ifgo[base + 1 * H_DIM + hc];
    float4 gv = *(const float4*)&g_ifgo[base + 2 * H_DIM + hc];
    float4 ov = *(const float4*)&g_ifgo[base + 3 * H_DIM + hc];
    float4 cv = *(const float4*)&c_t[(size_t)b * H_DIM + hc];

    float zi[4] = {iv.x, iv.y, iv.z, iv.w};
    float zf[4] = {fv.x, fv.y, fv.z, fv.w};
    float zg[4] = {gv.x, gv.y, gv.z, gv.w};
    float zo[4] = {ov.x, ov.y, ov.z, ov.w};
    float cc[4] = {cv.x, cv.y, cv.z, cv.w};

    float hn[4], cn[4];
    #pragma unroll
    for (int l = 0; l < 4; l++) {
        float bi_i = bi[0 * H_DIM + hc + l] + bh[0 * H_DIM + hc + l];
        float bi_f = bi[1 * H_DIM + hc + l] + bh[1 * H_DIM + hc + l];
        float bi_g = bi[2 * H_DIM + hc + l] + bh[2 * H_DIM + hc + l];
        float bi_o = bi[3 * H_DIM + hc + l] + bh[3 * H_DIM + hc + l];
        float ig = sigmoidf_fast(zi[l] + bi_i);
        float fg = sigmoidf_fast(zf[l] + bi_f);
        float gg = tanhf(zg[l] + bi_g);
        float og = sigmoidf_fast(zo[l] + bi_o);
        float c_new = fg * cc[l] + ig * gg;
        cn[l] = c_new;
        hn[l] = og * tanhf(c_new);
    }

    float4 hv  = {hn[0], hn[1], hn[2], hn[3]};
    float4 cvo = {cn[0], cn[1], cn[2], cn[3]};
    *(float4*)&out[(size_t)b * H_DIM + hc] = hv;
    *(float4*)&out[(size_t)B_DIM * H_DIM + (size_t)b * H_DIM + hc] = cvo;
}

// ---------------------------------------------------------------------------
// Launch. Inputs: input, h_t, c_t, w_i, w_h, b_i, b_h
// ---------------------------------------------------------------------------
extern "C" void kernel_launch(void* const* d_in, const int* in_sizes, int n_in,
                              void* d_out, int out_size)
{
    const float* x   = (const float*)d_in[0];
    const float* h_t = (const float*)d_in[1];
    const float* c_t = (const float*)d_in[2];
    const float* w_i = (const float*)d_in[3];
    const float* w_h = (const float*)d_in[4];
    const float* b_i = (const float*)d_in[5];
    const float* b_h = (const float*)d_in[6];
    float* out = (float*)d_out;

    dim3 grid(FOURH / BN, B_DIM / BM);   // 32 x 32
    lstm_gemm_tf32<<<grid, 128>>>(x, h_t, w_i, w_h);

    int n4 = B_DIM * (H_DIM / 4);
    lstm_gates_kernel<<<(n4 + 255) / 256, 256>>>(c_t, b_i, b_h, out);
}

// round 8
// speedup vs baseline: 4.9934x; 1.4315x over previous
#include <cuda_runtime.h>
#include <cstdint>
#include <cstddef>

// Problem dims (fixed)
#define B_DIM  4096
#define H_DIM  1024
#define FOURH  4096
#define K_DIM  2048

// GEMM tiling
#define BM 128
#define BN 128
#define BK 32
#define NSTAGE 3
#define NIT (K_DIM / BK)               // 64
#define STAGE_FLOATS 8192              // A 16KB + B 16KB
#define SMEM_BYTES (NSTAGE * STAGE_FLOATS * 4)   // 98304

// Fragment-ordered, tf32-pre-rounded operands (device scratch: allowed).
// g_A: [mblk(256)][kblk(256)][128]  fragment = m16k8, per-lane float4 {a0,a1,a2,a3}
// g_B: [nblk(512)][kpair(128)][128] fragment-pair = two k8n8 frags, {b0e,b1e,b0o,b1o}
__device__ float g_A[(size_t)B_DIM * K_DIM];
__device__ float g_B[(size_t)FOURH * K_DIM];
__device__ float g_bias[FOURH];   // permuted bias

// ---------------------------------------------------------------------------
__device__ __forceinline__ float rna_tf32_f(float x) {
    uint32_t r;
    asm("cvt.rna.tf32.f32 %0, %1;" : "=r"(r) : "f"(x));
    return __uint_as_float(r);
}
__device__ __forceinline__ uint32_t smem_u32(const void* p) {
    return (uint32_t)__cvta_generic_to_shared(p);
}
__device__ __forceinline__ void cp_async16(uint32_t dst, const void* src) {
    asm volatile("cp.async.cg.shared.global [%0], [%1], 16;\n" :: "r"(dst), "l"(src));
}
__device__ __forceinline__ float sig_f(float x) {
    return __fdividef(1.0f, 1.0f + __expf(-x));
}
__device__ __forceinline__ float tanh_f(float x) {
    // tanh(x) = 1 - 2/(exp(2x)+1); exact limits at +-inf, err ~1e-6
    return 1.0f - __fdividef(2.0f, __expf(2.0f * x) + 1.0f);
}
__device__ __forceinline__ void mma_tf32(float* c, const float4& a,
                                         uint32_t b0, uint32_t b1) {
    asm volatile(
        "mma.sync.aligned.m16n8k8.row.col.f32.tf32.tf32.f32 "
        "{%0,%1,%2,%3}, {%4,%5,%6,%7}, {%8,%9}, {%0,%1,%2,%3};\n"
        : "+f"(c[0]), "+f"(c[1]), "+f"(c[2]), "+f"(c[3])
        : "r"(__float_as_uint(a.x)), "r"(__float_as_uint(a.y)),
          "r"(__float_as_uint(a.z)), "r"(__float_as_uint(a.w)),
          "r"(b0), "r"(b1));
}

// ---------------------------------------------------------------------------
// Prepass A: round to tf32 + pack [x|h] into m16k8 fragment order.
// One warp per fragment (mblk, kblk). 65536 warps.
// ---------------------------------------------------------------------------
__global__ __launch_bounds__(256)
void prep_A(const float* __restrict__ x, const float* __restrict__ h)
{
    int w = blockIdx.x * 8 + (threadIdx.x >> 5);   // fragment id
    int lane = threadIdx.x & 31;
    int g = lane >> 2, tig = lane & 3;
    int mblk = w >> 8, kblk = w & 255;
    int m0 = mblk * 16, k0 = kblk * 8;

    const float* src = (k0 < H_DIM) ? x : h;
    int c0 = k0 & (H_DIM - 1);
    float a0 = src[(size_t)(m0 + g    ) * H_DIM + c0 + tig    ];
    float a1 = src[(size_t)(m0 + g + 8) * H_DIM + c0 + tig    ];
    float a2 = src[(size_t)(m0 + g    ) * H_DIM + c0 + tig + 4];
    float a3 = src[(size_t)(m0 + g + 8) * H_DIM + c0 + tig + 4];
    float4 v = make_float4(rna_tf32_f(a0), rna_tf32_f(a1),
                           rna_tf32_f(a2), rna_tf32_f(a3));
    *(float4*)&g_A[(size_t)w * 128 + lane * 4] = v;
}

// ---------------------------------------------------------------------------
// Prepass B: transpose W=[w_i;w_h], gate-interleave permute, round, pack as
// fragment pairs. Permutation: p = ublk*64 + gate*16 + uo  (ublk=u>>4, uo=u&15)
// One warp per (nblk, kpair). 65536 warps.
// ---------------------------------------------------------------------------
__global__ __launch_bounds__(256)
void prep_B(const float* __restrict__ wi, const float* __restrict__ wh)
{
    int w = blockIdx.x * 8 + (threadIdx.x >> 5);
    int lane = threadIdx.x & 31;
    int g = lane >> 2, tig = lane & 3;
    int nblk = w >> 7, kpair = w & 127;
    int p = nblk * 8 + g;
    int ublk = p >> 6, gate = (p >> 4) & 3, uo = p & 15;
    int n = gate * 1024 + ublk * 16 + uo;
    int k0 = kpair * 16;

    const float* src = (k0 < H_DIM) ? wi : wh;
    int r0 = k0 & (H_DIM - 1);
    float b0e = src[(size_t)(r0 + tig     ) * FOURH + n];
    float b1e = src[(size_t)(r0 + tig +  4) * FOURH + n];
    float b0o = src[(size_t)(r0 + tig +  8) * FOURH + n];
    float b1o = src[(size_t)(r0 + tig + 12) * FOURH + n];
    float4 v = make_float4(rna_tf32_f(b0e), rna_tf32_f(b1e),
                           rna_tf32_f(b0o), rna_tf32_f(b1o));
    *(float4*)&g_B[(size_t)w * 128 + lane * 4] = v;
}

__global__ __launch_bounds__(256)
void prep_bias(const float* __restrict__ bi, const float* __restrict__ bh)
{
    int p = blockIdx.x * 256 + threadIdx.x;
    if (p >= FOURH) return;
    int ublk = p >> 6, gate = (p >> 4) & 3, uo = p & 15;
    int n = gate * 1024 + ublk * 16 + uo;
    g_bias[p] = bi[n] + bh[n];
}

// ---------------------------------------------------------------------------
// Main GEMM + fused LSTM gates. 128 threads (4 warps x 64x64 warp tile),
// 3-stage cp.async pipeline, fragment-order smem (zero conflicts, LDS.128).
// ---------------------------------------------------------------------------
__global__ __launch_bounds__(128, 2)
void lstm_gemm_mma(const float* __restrict__ c_t, float* __restrict__ out)
{
    extern __shared__ float smem[];
    const int tid  = threadIdx.x;
    const int wid  = tid >> 5;
    const int lane = tid & 31;
    const int g    = lane >> 2;
    const int tig  = lane & 3;
    const int bm   = blockIdx.y * BM;
    const int bn   = blockIdx.x * BN;
    const int mblk0 = bm >> 4;    // 8 mblks per CTA
    const int nblk0 = bn >> 3;    // 16 nblks per CTA

    float acc[4][8][4];
    #pragma unroll
    for (int mt = 0; mt < 4; mt++)
        #pragma unroll
        for (int nt = 0; nt < 8; nt++)
            #pragma unroll
            for (int e = 0; e < 4; e++)
                acc[mt][nt][e] = 0.0f;

    // ---- stage loader: A = 8 x 2KB contiguous runs, B = 16 x 1KB runs ----
    #define LOAD_STAGE(s, it)                                                  \
    do {                                                                       \
        float* dstA = smem + (s) * STAGE_FLOATS;                               \
        const float* srcA = g_A + (size_t)mblk0 * 32768 + (size_t)(it) * 512;  \
        _Pragma("unroll")                                                      \
        for (int i = 0; i < 8; i++) {                                          \
            int q = tid + i * 128;                                             \
            int mb = q >> 7, rest = q & 127;                                   \
            cp_async16(smem_u32(dstA + q * 4),                                 \
                       srcA + (size_t)mb * 32768 + rest * 4);                  \
        }                                                                      \
        float* dstB = smem + (s) * STAGE_FLOATS + 4096;                        \
        const float* srcB = g_B + (size_t)nblk0 * 16384 + (size_t)(it) * 256;  \
        _Pragma("unroll")                                                      \
        for (int i = 0; i < 8; i++) {                                          \
            int q = tid + i * 128;                                             \
            int nb = q >> 6, rest = q & 63;                                    \
            cp_async16(smem_u32(dstB + q * 4),                                 \
                       srcB + (size_t)nb * 16384 + rest * 4);                  \
        }                                                                      \
        asm volatile("cp.async.commit_group;\n" ::: "memory");                 \
    } while (0)

    LOAD_STAGE(0, 0);
    LOAD_STAGE(1, 1);

    const int wmb = (wid >> 1) * 4;   // warp mblk base (wm = wmb*16)
    const int wnb = (wid & 1) * 8;    // warp nblk base (wn = wnb*8)

    for (int it = 0; it < NIT; it++) {
        if (it < NIT - 1)
            asm volatile("cp.async.wait_group 1;\n" ::: "memory");
        else
            asm volatile("cp.async.wait_group 0;\n" ::: "memory");
        __syncthreads();
        if (it + 2 < NIT) LOAD_STAGE((it + 2) % NSTAGE, it + 2);

        const int cur = it % NSTAGE;
        const float* As = smem + cur * STAGE_FLOATS + wmb * 512;
        const float* Bs = smem + cur * STAGE_FLOATS + 4096 + wnb * 256;

        #pragma unroll
        for (int kp = 0; kp < 2; kp++) {
            float4 bv[8];
            #pragma unroll
            for (int nt = 0; nt < 8; nt++)
                bv[nt] = *(const float4*)(Bs + (nt * 2 + kp) * 128 + lane * 4);
            #pragma unroll
            for (int kk = 0; kk < 2; kk++) {
                const int kblk = kp * 2 + kk;
                float4 av[4];
                #pragma unroll
                for (int mt = 0; mt < 4; mt++)
                    av[mt] = *(const float4*)(As + (mt * 4 + kblk) * 128 + lane * 4);
                #pragma unroll
                for (int mt = 0; mt < 4; mt++)
                    #pragma unroll
                    for (int nt = 0; nt < 8; nt++) {
                        uint32_t b0 = __float_as_uint(kk ? bv[nt].z : bv[nt].x);
                        uint32_t b1 = __float_as_uint(kk ? bv[nt].w : bv[nt].y);
                        mma_tf32(acc[mt][nt], av[mt], b0, b1);
                    }
            }
        }
    }
    #undef LOAD_STAGE

    // ---- fused LSTM gate epilogue (all register-local per thread) ----
    // Thread holds, for each of its (row, u) outputs, all 4 gates:
    //   gate G at nt = G*2 + hi, cols tig*2+{0,1}, rows g / g+8.
    const int wm   = (wid >> 1) * 64;
    const int wn   = (wid & 1) * 64;
    const int ublk = (bn + wn) >> 6;
    const int ucol = ublk * 16 + tig * 2;

    float2 bias2[8];
    #pragma unroll
    for (int nt = 0; nt < 8; nt++)
        bias2[nt] = *(const float2*)&g_bias[bn + wn + nt * 8 + tig * 2];

    #pragma unroll
    for (int mt = 0; mt < 4; mt++) {
        #pragma unroll
        for (int rs = 0; rs < 2; rs++) {
            const int row = bm + wm + mt * 16 + rs * 8 + g;
            #pragma unroll
            for (int hi = 0; hi < 2; hi++) {
                const int u = ucol + hi * 8;
                float2 cv = *(const float2*)&c_t[(size_t)row * H_DIM + u];
                float ce[2] = {cv.x, cv.y};
                float hn[2], cn[2];
                #pragma unroll
                for (int e = 0; e < 2; e++) {
                    float bi_i = e ? bias2[0 + hi].y : bias2[0 + hi].x;
                    float bi_f = e ? bias2[2 + hi].y : bias2[2 + hi].x;
                    float bi_g = e ? bias2[4 + hi].y : bias2[4 + hi].x;
                    float bi_o = e ? bias2[6 + hi].y : bias2[6 + hi].x;
                    float zi = acc[mt][0 + hi][rs * 2 + e] + bi_i;
                    float zf = acc[mt][2 + hi][rs * 2 + e] + bi_f;
                    float zg = acc[mt][4 + hi][rs * 2 + e] + bi_g;
                    float zo = acc[mt][6 + hi][rs * 2 + e] + bi_o;
                    float ig = sig_f(zi);
                    float fg = sig_f(zf);
                    float gg = tanh_f(zg);
                    float og = sig_f(zo);
                    float cnew = fg * ce[e] + ig * gg;
                    cn[e] = cnew;
                    hn[e] = og * tanh_f(cnew);
                }
                *(float2*)&out[(size_t)row * H_DIM + u] = make_float2(hn[0], hn[1]);
                *(float2*)&out[(size_t)B_DIM * H_DIM + (size_t)row * H_DIM + u] =
                    make_float2(cn[0], cn[1]);
            }
        }
    }
}

// ---------------------------------------------------------------------------
// Launch. Inputs: input, h_t, c_t, w_i, w_h, b_i, b_h
// ---------------------------------------------------------------------------
extern "C" void kernel_launch(void* const* d_in, const int* in_sizes, int n_in,
                              void* d_out, int out_size)
{
    const float* x   = (const float*)d_in[0];
    const float* h_t = (const float*)d_in[1];
    const float* c_t = (const float*)d_in[2];
    const float* w_i = (const float*)d_in[3];
    const float* w_h = (const float*)d_in[4];
    const float* b_i = (const float*)d_in[5];
    const float* b_h = (const float*)d_in[6];
    float* out = (float*)d_out;

    cudaFuncSetAttribute(lstm_gemm_mma,
                         cudaFuncAttributeMaxDynamicSharedMemorySize, SMEM_BYTES);

    prep_A<<<8192, 256>>>(x, h_t);
    prep_B<<<8192, 256>>>(w_i, w_h);
    prep_bias<<<FOURH / 256, 256>>>(b_i, b_h);

    lstm_gemm_mma<<<dim3(FOURH / BN, B_DIM / BM), 128, SMEM_BYTES>>>(c_t, out);
}

// round 11
// speedup vs baseline: 9.1910x; 1.8406x over previous
#include <cuda_runtime.h>
#include <cuda_fp16.h>
#include <cstdint>
#include <cstddef>

// Problem dims (fixed)
#define B_DIM  4096
#define H_DIM  1024
#define FOURH  4096
#define K_DIM  2048

// GEMM tiling
#define BM 128
#define BN 128
#define BK 64
#define NSTAGE 3
#define NIT (K_DIM / BK)               // 32
#define STAGE_U4 2048                  // 32KB per stage (A 16KB + B 16KB) in uint4
#define SMEM_BYTES (NSTAGE * 32768)    // 98304

// fp16 fragment-packed operands (device scratch).
// g_Ah: [mblk 256][k16 128][lane 32] uint4 = {a0,a1,a2,a3} of m16n8k16 A-frag
// g_Bh: [nblk 512][k32  64][lane 32] uint4 = {b0,b1 (k16#0), b0,b1 (k16#1)}
__device__ uint4 g_Ah[(size_t)256 * 128 * 32];
__device__ uint4 g_Bh[(size_t)512 * 64 * 32];
__device__ float g_bias[FOURH];   // permuted bias

// ---------------------------------------------------------------------------
__device__ __forceinline__ uint32_t pack_h2(float lo, float hi) {
    __half2 h = __floats2half2_rn(lo, hi);   // lo -> low 16 bits
    return *reinterpret_cast<uint32_t*>(&h);
}
__device__ __forceinline__ uint32_t smem_u32(const void* p) {
    return (uint32_t)__cvta_generic_to_shared(p);
}
__device__ __forceinline__ void cp_async16(uint32_t dst, const void* src) {
    asm volatile("cp.async.cg.shared.global [%0], [%1], 16;\n" :: "r"(dst), "l"(src));
}
__device__ __forceinline__ float sig_f(float x) {
    return __fdividef(1.0f, 1.0f + __expf(-x));
}
__device__ __forceinline__ float tanh_f(float x) {
    return 1.0f - __fdividef(2.0f, __expf(2.0f * x) + 1.0f);
}
__device__ __forceinline__ void mma_f16(float* c, const uint4& a,
                                        uint32_t b0, uint32_t b1) {
    asm volatile(
        "mma.sync.aligned.m16n8k16.row.col.f32.f16.f16.f32 "
        "{%0,%1,%2,%3}, {%4,%5,%6,%7}, {%8,%9}, {%0,%1,%2,%3};\n"
        : "+f"(c[0]), "+f"(c[1]), "+f"(c[2]), "+f"(c[3])
        : "r"(a.x), "r"(a.y), "r"(a.z), "r"(a.w), "r"(b0), "r"(b1));
}

// ---------------------------------------------------------------------------
// Prepass A: pack [x|h] (fp32) into fp16 m16n8k16 A-fragment order.
// One warp per (mblk, k16). 256*128 = 32768 warps.
// a0: row g,   k 2t..2t+1   | a1: row g+8, k 2t..2t+1
// a2: row g,   k 2t+8..2t+9 | a3: row g+8, k 2t+8..2t+9
// ---------------------------------------------------------------------------
__global__ __launch_bounds__(256)
void prep_A(const float* __restrict__ x, const float* __restrict__ h)
{
    int w = blockIdx.x * 8 + (threadIdx.x >> 5);
    int lane = threadIdx.x & 31;
    int g = lane >> 2, tig = lane & 3;
    int mblk = w >> 7, k16 = w & 127;
    int m0 = mblk * 16, k0 = k16 * 16;

    const float* src = (k0 < H_DIM) ? x : h;
    int c0 = k0 & (H_DIM - 1);
    const float* r_g  = src + (size_t)(m0 + g    ) * H_DIM + c0;
    const float* r_g8 = src + (size_t)(m0 + g + 8) * H_DIM + c0;
    float2 v0 = *(const float2*)(r_g  + 2 * tig);
    float2 v1 = *(const float2*)(r_g8 + 2 * tig);
    float2 v2 = *(const float2*)(r_g  + 2 * tig + 8);
    float2 v3 = *(const float2*)(r_g8 + 2 * tig + 8);

    uint4 out;
    out.x = pack_h2(v0.x, v0.y);
    out.y = pack_h2(v1.x, v1.y);
    out.z = pack_h2(v2.x, v2.y);
    out.w = pack_h2(v3.x, v3.y);
    g_Ah[(size_t)w * 32 + lane] = out;
}

// ---------------------------------------------------------------------------
// Prepass B: W=[w_i;w_h] transpose + gate-interleave permute + fp16 pack.
// One warp per (nblk, k32). 512*64 = 32768 warps.
// p = nblk*8 + g ; ublk=p>>6, gate=(p>>4)&3, uo=p&15 ; n = gate*1024+ublk*16+uo
// per k16 f: b0 = W[kb+2t..+1][n], b1 = W[kb+2t+8..+9][n]
// ---------------------------------------------------------------------------
__global__ __launch_bounds__(256)
void prep_B(const float* __restrict__ wi, const float* __restrict__ wh)
{
    int w = blockIdx.x * 8 + (threadIdx.x >> 5);
    int lane = threadIdx.x & 31;
    int g = lane >> 2, tig = lane & 3;
    int nblk = w >> 6, k32 = w & 63;
    int p = nblk * 8 + g;
    int ublk = p >> 6, gate = (p >> 4) & 3, uo = p & 15;
    int n = gate * 1024 + ublk * 16 + uo;
    int k0 = k32 * 32;

    const float* src = (k0 < H_DIM) ? wi : wh;
    int r0 = k0 & (H_DIM - 1);

    uint4 out;
    #pragma unroll
    for (int f = 0; f < 2; f++) {
        int kb = r0 + f * 16;
        float e0 = src[(size_t)(kb + 2 * tig    ) * FOURH + n];
        float e1 = src[(size_t)(kb + 2 * tig + 1) * FOURH + n];
        float e2 = src[(size_t)(kb + 2 * tig + 8) * FOURH + n];
        float e3 = src[(size_t)(kb + 2 * tig + 9) * FOURH + n];
        uint32_t b0 = pack_h2(e0, e1);
        uint32_t b1 = pack_h2(e2, e3);
        if (f == 0) { out.x = b0; out.y = b1; }
        else        { out.z = b0; out.w = b1; }
    }
    g_Bh[(size_t)w * 32 + lane] = out;
}

__global__ __launch_bounds__(256)
void prep_bias(const float* __restrict__ bi, const float* __restrict__ bh)
{
    int p = blockIdx.x * 256 + threadIdx.x;
    if (p >= FOURH) return;
    int ublk = p >> 6, gate = (p >> 4) & 3, uo = p & 15;
    int n = gate * 1024 + ublk * 16 + uo;
    g_bias[p] = bi[n] + bh[n];
}

// ---------------------------------------------------------------------------
// Main GEMM (fp16 MMA, fp32 accum) + fused LSTM gates.
// 128 threads, 4 warps x (64x64), BK=64, 3-stage cp.async pipeline.
// ---------------------------------------------------------------------------
__global__ __launch_bounds__(128, 2)
void lstm_gemm_mma(const float* __restrict__ c_t, float* __restrict__ out)
{
    extern __shared__ uint4 smem[];
    const int tid  = threadIdx.x;
    const int wid  = tid >> 5;
    const int lane = tid & 31;
    const int g    = lane >> 2;
    const int tig  = lane & 3;
    const int bm   = blockIdx.y * BM;
    const int bn   = blockIdx.x * BN;
    const int mblk0 = bm >> 4;    // 8 mblks per CTA
    const int nblk0 = bn >> 3;    // 16 nblks per CTA

    float acc[4][8][4];
    #pragma unroll
    for (int mt = 0; mt < 4; mt++)
        #pragma unroll
        for (int nt = 0; nt < 8; nt++)
            #pragma unroll
            for (int e = 0; e < 4; e++)
                acc[mt][nt][e] = 0.0f;

    // Stage layout (uint4 units): A [mb 8][k16 4][lane 32] then B [nb 16][k32 2][lane 32]
    #define LOAD_STAGE(s, it)                                                  \
    do {                                                                       \
        uint4* dst = smem + (s) * STAGE_U4;                                    \
        const uint4* srcA = g_Ah + (size_t)mblk0 * 4096 + (size_t)(it) * 128;  \
        _Pragma("unroll")                                                      \
        for (int i = 0; i < 8; i++) {                                          \
            int q = tid + i * 128;                                             \
            int mb = q >> 7, rest = q & 127;                                   \
            cp_async16(smem_u32(dst + q), srcA + (size_t)mb * 4096 + rest);    \
        }                                                                      \
        const uint4* srcB = g_Bh + (size_t)nblk0 * 2048 + (size_t)(it) * 64;   \
        _Pragma("unroll")                                                      \
        for (int i = 0; i < 8; i++) {                                          \
            int q = tid + i * 128;                                             \
            int nb = q >> 6, rest = q & 63;                                    \
            cp_async16(smem_u32(dst + 1024 + q),                               \
                       srcB + (size_t)nb * 2048 + rest);                       \
        }                                                                      \
        asm volatile("cp.async.commit_group;\n" ::: "memory");                 \
    } while (0)

    LOAD_STAGE(0, 0);
    LOAD_STAGE(1, 1);

    const int wmb = (wid >> 1) * 4;   // warp mblk base
    const int wnb = (wid & 1) * 8;    // warp nblk base

    for (int it = 0; it < NIT; it++) {
        if (it < NIT - 1)
            asm volatile("cp.async.wait_group 1;\n" ::: "memory");
        else
            asm volatile("cp.async.wait_group 0;\n" ::: "memory");
        __syncthreads();
        if (it + 2 < NIT) LOAD_STAGE((it + 2) % NSTAGE, it + 2);

        const uint4* As = smem + (it % NSTAGE) * STAGE_U4 + wmb * 128 + lane;
        const uint4* Bs = smem + (it % NSTAGE) * STAGE_U4 + 1024 + wnb * 64 + lane;

        #pragma unroll
        for (int kp = 0; kp < 2; kp++) {          // two k32 halves of BK=64
            uint4 bv[8];
            #pragma unroll
            for (int nt = 0; nt < 8; nt++)
                bv[nt] = Bs[nt * 64 + kp * 32];
            #pragma unroll
            for (int kk = 0; kk < 2; kk++) {      // two k16 steps per k32
                uint4 av[4];
                #pragma unroll
                for (int mt = 0; mt < 4; mt++)
                    av[mt] = As[mt * 128 + (kp * 2 + kk) * 32];
                #pragma unroll
                for (int mt = 0; mt < 4; mt++)
                    #pragma unroll
                    for (int nt = 0; nt < 8; nt++) {
                        uint32_t b0 = kk ? bv[nt].z : bv[nt].x;
                        uint32_t b1 = kk ? bv[nt].w : bv[nt].y;
                        mma_f16(acc[mt][nt], av[mt], b0, b1);
                    }
            }
        }
    }
    #undef LOAD_STAGE

    // ---- fused LSTM gate epilogue (register-local; C layout = m16n8) ----
    const int wm   = (wid >> 1) * 64;
    const int wn   = (wid & 1) * 64;
    const int ublk = (bn + wn) >> 6;
    const int ucol = ublk * 16 + tig * 2;

    float2 bias2[8];
    #pragma unroll
    for (int nt = 0; nt < 8; nt++)
        bias2[nt] = *(const float2*)&g_bias[bn + wn + nt * 8 + tig * 2];

    #pragma unroll
    for (int mt = 0; mt < 4; mt++) {
        #pragma unroll
        for (int rs = 0; rs < 2; rs++) {
            const int row = bm + wm + mt * 16 + rs * 8 + g;
            #pragma unroll
            for (int hi = 0; hi < 2; hi++) {
                const int u = ucol + hi * 8;
                float2 cv = *(const float2*)&c_t[(size_t)row * H_DIM + u];
                float ce[2] = {cv.x, cv.y};
                float hn[2], cn[2];
                #pragma unroll
                for (int e = 0; e < 2; e++) {
                    float bi_i = e ? bias2[0 + hi].y : bias2[0 + hi].x;
                    float bi_f = e ? bias2[2 + hi].y : bias2[2 + hi].x;
                    float bi_g = e ? bias2[4 + hi].y : bias2[4 + hi].x;
                    float bi_o = e ? bias2[6 + hi].y : bias2[6 + hi].x;
                    float zi = acc[mt][0 + hi][rs * 2 + e] + bi_i;
                    float zf = acc[mt][2 + hi][rs * 2 + e] + bi_f;
                    float zg = acc[mt][4 + hi][rs * 2 + e] + bi_g;
                    float zo = acc[mt][6 + hi][rs * 2 + e] + bi_o;
                    float ig = sig_f(zi);
                    float fg = sig_f(zf);
                    float gg = tanh_f(zg);
                    float og = sig_f(zo);
                    float cnew = fg * ce[e] + ig * gg;
                    cn[e] = cnew;
                    hn[e] = og * tanh_f(cnew);
                }
                *(float2*)&out[(size_t)row * H_DIM + u] = make_float2(hn[0], hn[1]);
                *(float2*)&out[(size_t)B_DIM * H_DIM + (size_t)row * H_DIM + u] =
                    make_float2(cn[0], cn[1]);
            }
        }
    }
}

// ---------------------------------------------------------------------------
// Launch. Inputs: input, h_t, c_t, w_i, w_h, b_i, b_h
// ---------------------------------------------------------------------------
extern "C" void kernel_launch(void* const* d_in, const int* in_sizes, int n_in,
                              void* d_out, int out_size)
{
    const float* x   = (const float*)d_in[0];
    const float* h_t = (const float*)d_in[1];
    const float* c_t = (const float*)d_in[2];
    const float* w_i = (const float*)d_in[3];
    const float* w_h = (const float*)d_in[4];
    const float* b_i = (const float*)d_in[5];
    const float* b_h = (const float*)d_in[6];
    float* out = (float*)d_out;

    cudaFuncSetAttribute(lstm_gemm_mma,
                         cudaFuncAttributeMaxDynamicSharedMemorySize, SMEM_BYTES);

    prep_A<<<4096, 256>>>(x, h_t);
    prep_B<<<4096, 256>>>(w_i, w_h);
    prep_bias<<<FOURH / 256, 256>>>(b_i, b_h);

    lstm_gemm_mma<<<dim3(FOURH / BN, B_DIM / BM), 128, SMEM_BYTES>>>(c_t, out);
}